// round 7
// baseline (speedup 1.0000x reference)
#include <cuda_runtime.h>
#include <cstdint>

#define B_  1024
#define G_  2000
#define S_  32
#define H_  64
#define NGC 20              // gene-GEMM split-K chunks (K=100 each)
#define NCHUNK (NGC + 14)   // + 8 (z1) + 4 (z2) + 2 (z3)
#define NZBLK  224          // 14 z-chunks * 16 row tiles
#define NPSEG  20           // 100-gene segments per row (12800 B each)
#define NBGRP  16           // groups of 64 batch rows
#define GENEBLK (NPSEG * NBGRP)   // 320
#define CHUNK_BYTES 12800
#define CHUNK_FLOATS 3200
#define ROWSTRIDE (G_ * S_)       // 64000 floats per x row

// Scratch (static device globals — allocation-free per harness rules)
__device__ float g_gene[B_ * G_];            // 8 MB
__device__ float g_part[NCHUNK * B_ * H_];   // 8.9 MB

// ---------------- packed fp32x2 helpers (sm_103a full-rate FMA path) ----------
__device__ __forceinline__ unsigned long long dup2(float v) {
    unsigned long long r;
    asm("mov.b64 %0, {%1, %1};" : "=l"(r) : "f"(v));
    return r;
}
__device__ __forceinline__ void ffma2(unsigned long long& d,
                                      unsigned long long a, unsigned long long b) {
    asm("fma.rn.f32x2 %0, %1, %2, %0;" : "+l"(d) : "l"(a), "l"(b));
}
__device__ __forceinline__ float2 unpk(unsigned long long v) {
    float2 r;
    asm("mov.b64 {%0, %1}, %2;" : "=f"(r.x), "=f"(r.y) : "l"(v));
    return r;
}

// ---------------- bulk-async + mbarrier primitives ----------------------------
__device__ __forceinline__ uint32_t smem_u32(const void* p) {
    uint32_t a;
    asm("{ .reg .u64 t; cvta.to.shared.u64 t, %1; cvt.u32.u64 %0, t; }"
        : "=r"(a) : "l"(p));
    return a;
}
__device__ __forceinline__ void mbar_init(uint32_t mb, uint32_t cnt) {
    asm volatile("mbarrier.init.shared.b64 [%0], %1;" :: "r"(mb), "r"(cnt) : "memory");
}
__device__ __forceinline__ void mbar_expect_tx(uint32_t mb, uint32_t bytes) {
    asm volatile("mbarrier.arrive.expect_tx.shared.b64 _, [%0], %1;"
                 :: "r"(mb), "r"(bytes) : "memory");
}
__device__ __forceinline__ void bulk_g2s(uint32_t dst, const void* src,
                                         uint32_t bytes, uint32_t mb) {
    asm volatile("cp.async.bulk.shared::cta.global.mbarrier::complete_tx::bytes "
                 "[%0], [%1], %2, [%3];"
                 :: "r"(dst), "l"(src), "r"(bytes), "r"(mb) : "memory");
}
__device__ __forceinline__ void mbar_wait(uint32_t mb, uint32_t parity) {
    asm volatile(
        "{\n\t.reg .pred P;\n"
        "W%=:\n\tmbarrier.try_wait.parity.acquire.cta.shared::cta.b64 P, [%0], %1, 0x989680;\n"
        "\t@P bra D%=;\n\tbra W%=;\n"
        "D%=:\n\t}"
        :: "r"(mb), "r"(parity) : "memory");
}
__device__ __forceinline__ void fence_proxy_async_cta() {
    asm volatile("fence.proxy.async.shared::cta;" ::: "memory");
}

// =============================================================================
// GEMM body (single-buffered smem staging, pointers into the shared union):
// one 64x64 output tile over a <=512-wide K chunk; partial into g_part[c].
// =============================================================================
template <bool STREAM_A>
__device__ __forceinline__ void gemm_body(float* __restrict__ As,   // [32][66]
                                          float* __restrict__ Bs,   // [32*64]
                                          const float* __restrict__ A,
                                          const float* __restrict__ W,
                                          int lda, int k0, int klen,
                                          int c, int row0)
{
    const float* Ab = A + (size_t)row0 * lda + k0;
    const float* Wb = W + (size_t)k0 * 64;

    const int t    = threadIdx.x;
    const int tx   = t & 15;
    const int ty   = t >> 4;
    const int arow = t >> 3;
    const int af4  = (t & 7) * 4;
    const int ksteps = (klen + 31) >> 5;

    unsigned long long acc[2][4];
    #pragma unroll
    for (int p = 0; p < 2; p++)
        #pragma unroll
        for (int q = 0; q < 4; q++) acc[p][q] = 0ull;

    for (int ks = 0; ks < ksteps; ks++) {
        const int kk = ks * 32;
        const int kg = kk + af4;

        float4 av[2];
        #pragma unroll
        for (int i = 0; i < 2; i++) {
            const float* ap = Ab + (size_t)(arow + 32 * i) * lda;
            float4 v;
            if (kg + 3 < klen) {
                v = STREAM_A ? __ldcs((const float4*)(ap + kg))
                             : *(const float4*)(ap + kg);
            } else {
                v.x = (kg + 0 < klen) ? ap[kg + 0] : 0.0f;
                v.y = (kg + 1 < klen) ? ap[kg + 1] : 0.0f;
                v.z = (kg + 2 < klen) ? ap[kg + 2] : 0.0f;
                v.w = (kg + 3 < klen) ? ap[kg + 3] : 0.0f;
            }
            av[i] = v;
        }
        float4 bv2[2];
        #pragma unroll
        for (int i = 0; i < 2; i++) {
            const int q  = t + 256 * i;
            const int kr = kk + (q >> 4);
            float4 v = make_float4(0.f, 0.f, 0.f, 0.f);
            if (kr < klen) v = *(const float4*)(Wb + (size_t)kr * 64 + (q & 15) * 4);
            bv2[i] = v;
        }

        __syncthreads();
        #pragma unroll
        for (int i = 0; i < 2; i++) {
            As[(af4 + 0) * 66 + arow + 32 * i] = av[i].x;
            As[(af4 + 1) * 66 + arow + 32 * i] = av[i].y;
            As[(af4 + 2) * 66 + arow + 32 * i] = av[i].z;
            As[(af4 + 3) * 66 + arow + 32 * i] = av[i].w;
        }
        *(float4*)(Bs + (size_t)t * 4)         = bv2[0];
        *(float4*)(Bs + (size_t)(t + 256) * 4) = bv2[1];
        __syncthreads();

        #pragma unroll
        for (int k = 0; k < 32; k++) {
            const unsigned long long A0 = *(const unsigned long long*)&As[k * 66 + ty * 4];
            const unsigned long long A1 = *(const unsigned long long*)&As[k * 66 + ty * 4 + 2];
            const float4 bv = *(const float4*)(Bs + k * 64 + tx * 4);
            const unsigned long long Bq0 = dup2(bv.x);
            const unsigned long long Bq1 = dup2(bv.y);
            const unsigned long long Bq2 = dup2(bv.z);
            const unsigned long long Bq3 = dup2(bv.w);
            ffma2(acc[0][0], A0, Bq0); ffma2(acc[1][0], A1, Bq0);
            ffma2(acc[0][1], A0, Bq1); ffma2(acc[1][1], A1, Bq1);
            ffma2(acc[0][2], A0, Bq2); ffma2(acc[1][2], A1, Bq2);
            ffma2(acc[0][3], A0, Bq3); ffma2(acc[1][3], A1, Bq3);
        }
    }

    float* outp = g_part + ((size_t)c * B_ + row0 + ty * 4) * 64 + tx * 4;
    #pragma unroll
    for (int p = 0; p < 2; p++) {
        const float2 u0 = unpk(acc[p][0]);
        const float2 u1 = unpk(acc[p][1]);
        const float2 u2 = unpk(acc[p][2]);
        const float2 u3 = unpk(acc[p][3]);
        *(float4*)(outp + (size_t)(2 * p) * 64)     = make_float4(u0.x, u1.x, u2.x, u3.x);
        *(float4*)(outp + (size_t)(2 * p + 1) * 64) = make_float4(u0.y, u1.y, u2.y, u3.y);
    }
}

// =============================================================================
// Fused kernel.
//  blocks [0, NZBLK):   14 z-GEMM chunks x 16 row tiles (per-lane LDG path)
//  blocks [NZBLK, 544): gene stage via cp.async.bulk pipeline:
//    block owns (100-gene segment, 64 batch rows). Wg segment staged once in
//    smem; per row ONE 12.8KB contiguous bulk copy gmem->smem (2-stage
//    mbarrier ring) — zero per-lane LDG for x, DMA path bypasses L1tex.
// =============================================================================
__global__ void __launch_bounds__(256, 4) fused_kernel(
    const float* __restrict__ x,
    const float* __restrict__ z1, const float* __restrict__ z2,
    const float* __restrict__ z3,
    const float* __restrict__ Wg, const float* __restrict__ bg,
    const float* __restrict__ W1, const float* __restrict__ W2,
    const float* __restrict__ W3)
{
    __shared__ __align__(128) unsigned char smraw[3 * CHUNK_BYTES];  // 38400 B
    __shared__ __align__(8)   unsigned long long mbar[2];

    const int bid = blockIdx.x;
    if (bid < NZBLK) {
        float* As = (float*)smraw;                   // 8448 B as [32][66]
        float* Bs = (float*)(smraw + 8448);          // 8192 B
        const int zc   = bid >> 4;            // 0..13
        const int row0 = (bid & 15) * 64;
        const float* A; const float* W; int lda, k0;
        if (zc < 8)       { A = z1; W = W1; lda = 4096; k0 = zc * 512; }
        else if (zc < 12) { A = z2; W = W2; lda = 2048; k0 = (zc - 8)  * 512; }
        else              { A = z3; W = W3; lda = 1024; k0 = (zc - 12) * 512; }
        gemm_body<true>(As, Bs, A, W, lda, k0, 512, NGC + zc, row0);
        return;
    }

    // ---- gene population ----
    float* sX0 = (float*)smraw;                       // stage 0: 12800 B
    float* sX1 = (float*)(smraw + CHUNK_BYTES);       // stage 1: 12800 B
    float* sW  = (float*)(smraw + 2 * CHUNK_BYTES);   // Wg seg:  12800 B

    const int gb   = bid - NZBLK;
    const int pseg = gb % NPSEG;             // 0..19  (100-gene segment)
    const int b0   = (gb / NPSEG) * 64;      // 0..960 (64-row group)

    const int t    = threadIdx.x;
    const int lane = t & 31;
    const int warp = t >> 5;

    // stage Wg segment (L2-resident) into smem
    const float* wseg = Wg + (size_t)pseg * CHUNK_FLOATS;
    for (int i = t; i < CHUNK_FLOATS; i += 256) sW[i] = wseg[i];

    // per-lane bias values for this warp's items (leaders use them)
    float biasr[4];
    #pragma unroll
    for (int j = 0; j < 4; j++) {
        const int it = warp + 8 * j;
        biasr[j] = (it < 25) ? __ldg(bg + pseg * 100 + it * 4 + (lane >> 3)) : 0.0f;
    }
    const bool store_lane = (lane & 7) == 0;

    const uint32_t mb0 = smem_u32(&mbar[0]);
    const uint32_t mb1 = smem_u32(&mbar[1]);
    const uint32_t sx0 = smem_u32(sX0);
    const uint32_t sx1 = smem_u32(sX1);

    if (t == 0) { mbar_init(mb0, 1); mbar_init(mb1, 1); }
    __syncthreads();

    const float* xg = x + (size_t)b0 * ROWSTRIDE + (size_t)pseg * CHUNK_FLOATS;

    if (t == 0) {
        fence_proxy_async_cta();
        mbar_expect_tx(mb0, CHUNK_BYTES);
        bulk_g2s(sx0, xg, CHUNK_BYTES, mb0);
        mbar_expect_tx(mb1, CHUNK_BYTES);
        bulk_g2s(sx1, xg + ROWSTRIDE, CHUNK_BYTES, mb1);
    }

    for (int cc = 0; cc < 64; cc++) {
        const int s       = cc & 1;
        const uint32_t pr = (cc >> 1) & 1;
        mbar_wait(s ? mb1 : mb0, pr);

        const float* xs = s ? sX1 : sX0;
        float* gp = g_gene + (size_t)(b0 + cc) * G_ + pseg * 100;

        #pragma unroll
        for (int j = 0; j < 4; j++) {
            const int it = warp + 8 * j;
            if (it < 25) {
                const float4 xv = *(const float4*)(xs + it * 128 + lane * 4);
                const float4 wv = *(const float4*)(sW + it * 128 + lane * 4);
                float d = xv.x * wv.x + xv.y * wv.y + xv.z * wv.z + xv.w * wv.w;
                d += __shfl_down_sync(0xffffffffu, d, 4);
                d += __shfl_down_sync(0xffffffffu, d, 2);
                d += __shfl_down_sync(0xffffffffu, d, 1);
                if (store_lane)
                    gp[it * 4 + (lane >> 3)] = fmaxf(d + biasr[j], 0.0f);
            }
        }
        __syncthreads();   // all threads consumed stage s

        if (t == 0 && cc + 2 < 64) {
            const uint32_t mb = s ? mb1 : mb0;
            mbar_expect_tx(mb, CHUNK_BYTES);
            bulk_g2s(s ? sx1 : sx0, xg + (size_t)(cc + 2) * ROWSTRIDE,
                     CHUNK_BYTES, mb);
        }
    }
}

// =============================================================================
// Gene-GEMM kernel: NGC chunks (K=100 each), 16 x 20 = 320 blocks.
// =============================================================================
__global__ void __launch_bounds__(256, 5) gene_gemm_kernel(const float* __restrict__ W0)
{
    __shared__ __align__(128) float As[32 * 66];
    __shared__ __align__(128) float Bs[32 * 64];
    const int c    = blockIdx.y;                  // 0..NGC-1
    const int row0 = blockIdx.x * 64;
    gemm_body<false>(As, Bs, g_gene, W0, G_, c * 100, 100, c, row0);
}

// =============================================================================
// Finish kernel: reduce split-K partials, fusion, final 64->64->64->1 MLP.
// =============================================================================
__global__ void __launch_bounds__(256) finish_kernel(
    const float* __restrict__ b0, const float* __restrict__ b1,
    const float* __restrict__ b2, const float* __restrict__ b3,
    const float* __restrict__ w1, const float* __restrict__ w2,
    const float* __restrict__ w3,
    const float* __restrict__ fW1, const float* __restrict__ fb1,
    const float* __restrict__ fW2, const float* __restrict__ fb2,
    const float* __restrict__ fW3, const float* __restrict__ fb3,
    float* __restrict__ out)
{
    __shared__ float sW1[64 * 64];
    __shared__ float sW2[64 * 64];
    __shared__ float sbuf[4][64];
    __shared__ float sred[8];

    const int t = threadIdx.x;
    const int h = t & 63;
    const int r = t >> 6;
    for (int i = t; i < 64 * 64; i += 256) { sW1[i] = fW1[i]; sW2[i] = fW2[i]; }

    const int b = blockIdx.x * 4 + r;

    float a0 = 0.f, a1 = 0.f, a2 = 0.f, a3 = 0.f;
    #pragma unroll
    for (int cc = 0;       cc < NGC;      cc++) a0 += g_part[((size_t)cc * B_ + b) * 64 + h];
    #pragma unroll
    for (int cc = NGC;     cc < NGC + 8;  cc++) a1 += g_part[((size_t)cc * B_ + b) * 64 + h];
    #pragma unroll
    for (int cc = NGC + 8; cc < NGC + 12; cc++) a2 += g_part[((size_t)cc * B_ + b) * 64 + h];
    #pragma unroll
    for (int cc = NGC + 12; cc < NGC + 14; cc++) a3 += g_part[((size_t)cc * B_ + b) * 64 + h];

    float d = fmaxf(a0 + b0[h], 0.f);
    d += fmaxf(a1 + b1[h], 0.f) * w1[h];
    d += fmaxf(a2 + b2[h], 0.f) * w2[h];
    d += fmaxf(a3 + b3[h], 0.f) * w3[h];

    __syncthreads();
    sbuf[r][h] = d;
    __syncthreads();
    float acc = fb1[h];
    #pragma unroll
    for (int k = 0; k < 64; k++) acc = fmaf(sbuf[r][k], sW1[k * 64 + h], acc);
    const float hv = fmaxf(acc, 0.f);
    __syncthreads();
    sbuf[r][h] = hv;
    __syncthreads();
    acc = fb2[h];
    #pragma unroll
    for (int k = 0; k < 64; k++) acc = fmaf(sbuf[r][k], sW2[k * 64 + h], acc);
    const float h2 = fmaxf(acc, 0.f);

    float val = h2 * fW3[h];
    #pragma unroll
    for (int off = 16; off; off >>= 1) val += __shfl_down_sync(0xffffffffu, val, off);
    if ((t & 31) == 0) sred[t >> 5] = val;
    __syncthreads();
    if (h == 0) out[b] = sred[2 * r] + sred[2 * r + 1] + fb3[0];
}

// =============================================================================
// Launcher (graph-capturable: 3 kernel launches, no sync, no alloc)
// =============================================================================
extern "C" void kernel_launch(void* const* d_in, const int* in_sizes, int n_in,
                              void* d_out, int out_size)
{
    const float* x   = (const float*)d_in[0];
    const float* z1  = (const float*)d_in[1];
    const float* z2  = (const float*)d_in[2];
    const float* z3  = (const float*)d_in[3];
    const float* Wg  = (const float*)d_in[4];
    const float* bg  = (const float*)d_in[5];
    const float* W0  = (const float*)d_in[6];
    const float* b0  = (const float*)d_in[7];
    const float* W1  = (const float*)d_in[8];
    const float* b1  = (const float*)d_in[9];
    const float* W2  = (const float*)d_in[10];
    const float* b2  = (const float*)d_in[11];
    const float* W3  = (const float*)d_in[12];
    const float* b3  = (const float*)d_in[13];
    const float* w1  = (const float*)d_in[14];
    const float* w2  = (const float*)d_in[15];
    const float* w3  = (const float*)d_in[16];
    const float* fW1 = (const float*)d_in[17];
    const float* fb1 = (const float*)d_in[18];
    const float* fW2 = (const float*)d_in[19];
    const float* fb2 = (const float*)d_in[20];
    const float* fW3 = (const float*)d_in[21];
    const float* fb3 = (const float*)d_in[22];
    float* out = (float*)d_out;

    fused_kernel<<<NZBLK + GENEBLK, 256>>>(x, z1, z2, z3, Wg, bg, W1, W2, W3);
    gene_gemm_kernel<<<dim3(B_ / 64, NGC), 256>>>(W0);
    finish_kernel<<<B_ / 4, 256>>>(b0, b1, b2, b3, w1, w2, w3,
                                   fW1, fb1, fW2, fb2, fW3, fb3, out);
}

// round 8
// speedup vs baseline: 1.2420x; 1.2420x over previous
#include <cuda_runtime.h>

#define B_  1024
#define G_  2000
#define S_  32
#define H_  64
#define NGC 20           // gene-GEMM split-K chunks (K=100 each)
#define NCHUNK (NGC + 14)   // + 8 (z1) + 4 (z2) + 2 (z3)
#define NZBLK  224       // 14 z-chunks * 16 row tiles
#define GENEBLK 250      // 2000 gene warp-tasks / 8 warps per block (R4 layout)
#define ROWSTRIDE (G_ * S_)   // 64000 floats per x row

// Scratch (static device globals — allocation-free per harness rules)
__device__ float g_gene[B_ * G_];            // 8 MB
__device__ float g_part[NCHUNK * B_ * H_];   // 8.9 MB

// ---------------- packed fp32x2 helpers (sm_103a full-rate FMA path) ----------
__device__ __forceinline__ unsigned long long dup2(float v) {
    unsigned long long r;
    asm("mov.b64 %0, {%1, %1};" : "=l"(r) : "f"(v));
    return r;
}
__device__ __forceinline__ void ffma2(unsigned long long& d,
                                      unsigned long long a, unsigned long long b) {
    asm("fma.rn.f32x2 %0, %1, %2, %0;" : "+l"(d) : "l"(a), "l"(b));
}
__device__ __forceinline__ float2 unpk(unsigned long long v) {
    float2 r;
    asm("mov.b64 {%0, %1}, %2;" : "=f"(r.x), "=f"(r.y) : "l"(v));
    return r;
}

// =============================================================================
// GEMM body (single-buffered smem staging): one 64x64 output tile over a
// <=512-wide K chunk; deterministic partial into g_part[c].
// =============================================================================
template <bool STREAM_A>
__device__ __forceinline__ void gemm_body(const float* __restrict__ A,
                                          const float* __restrict__ W,
                                          int lda, int k0, int klen,
                                          int c, int row0)
{
    __shared__ float As[32][66];
    __shared__ float Bs[32 * 64];

    const float* Ab = A + (size_t)row0 * lda + k0;
    const float* Wb = W + (size_t)k0 * 64;

    const int t    = threadIdx.x;
    const int tx   = t & 15;
    const int ty   = t >> 4;
    const int arow = t >> 3;
    const int af4  = (t & 7) * 4;
    const int ksteps = (klen + 31) >> 5;

    unsigned long long acc[2][4];
    #pragma unroll
    for (int p = 0; p < 2; p++)
        #pragma unroll
        for (int q = 0; q < 4; q++) acc[p][q] = 0ull;

    for (int ks = 0; ks < ksteps; ks++) {
        const int kk = ks * 32;
        const int kg = kk + af4;

        float4 av[2];
        #pragma unroll
        for (int i = 0; i < 2; i++) {
            const float* ap = Ab + (size_t)(arow + 32 * i) * lda;
            float4 v;
            if (kg + 3 < klen) {
                v = STREAM_A ? __ldcs((const float4*)(ap + kg))
                             : *(const float4*)(ap + kg);
            } else {
                v.x = (kg + 0 < klen) ? ap[kg + 0] : 0.0f;
                v.y = (kg + 1 < klen) ? ap[kg + 1] : 0.0f;
                v.z = (kg + 2 < klen) ? ap[kg + 2] : 0.0f;
                v.w = (kg + 3 < klen) ? ap[kg + 3] : 0.0f;
            }
            av[i] = v;
        }
        float4 bv2[2];
        #pragma unroll
        for (int i = 0; i < 2; i++) {
            const int q  = t + 256 * i;
            const int kr = kk + (q >> 4);
            float4 v = make_float4(0.f, 0.f, 0.f, 0.f);
            if (kr < klen) v = *(const float4*)(Wb + (size_t)kr * 64 + (q & 15) * 4);
            bv2[i] = v;
        }

        __syncthreads();
        #pragma unroll
        for (int i = 0; i < 2; i++) {
            As[af4 + 0][arow + 32 * i] = av[i].x;
            As[af4 + 1][arow + 32 * i] = av[i].y;
            As[af4 + 2][arow + 32 * i] = av[i].z;
            As[af4 + 3][arow + 32 * i] = av[i].w;
        }
        *(float4*)(Bs + (size_t)t * 4)         = bv2[0];
        *(float4*)(Bs + (size_t)(t + 256) * 4) = bv2[1];
        __syncthreads();

        #pragma unroll
        for (int k = 0; k < 32; k++) {
            const unsigned long long A0 = *(const unsigned long long*)&As[k][ty * 4];
            const unsigned long long A1 = *(const unsigned long long*)&As[k][ty * 4 + 2];
            const float4 bv = *(const float4*)(Bs + k * 64 + tx * 4);
            const unsigned long long Bq0 = dup2(bv.x);
            const unsigned long long Bq1 = dup2(bv.y);
            const unsigned long long Bq2 = dup2(bv.z);
            const unsigned long long Bq3 = dup2(bv.w);
            ffma2(acc[0][0], A0, Bq0); ffma2(acc[1][0], A1, Bq0);
            ffma2(acc[0][1], A0, Bq1); ffma2(acc[1][1], A1, Bq1);
            ffma2(acc[0][2], A0, Bq2); ffma2(acc[1][2], A1, Bq2);
            ffma2(acc[0][3], A0, Bq3); ffma2(acc[1][3], A1, Bq3);
        }
    }

    float* outp = g_part + ((size_t)c * B_ + row0 + ty * 4) * 64 + tx * 4;
    #pragma unroll
    for (int p = 0; p < 2; p++) {
        const float2 u0 = unpk(acc[p][0]);
        const float2 u1 = unpk(acc[p][1]);
        const float2 u2 = unpk(acc[p][2]);
        const float2 u3 = unpk(acc[p][3]);
        *(float4*)(outp + (size_t)(2 * p) * 64)     = make_float4(u0.x, u1.x, u2.x, u3.x);
        *(float4*)(outp + (size_t)(2 * p + 1) * 64) = make_float4(u0.y, u1.y, u2.y, u3.y);
    }
}

// =============================================================================
// Fused kernel (R4 layout — measured best: 65.8us @ 57.6% DRAM).
//  blocks [0, NZBLK):        14 z-GEMM chunks x 16 row tiles
//  blocks [NZBLK, NZBLK+250): gene stage. One warp owns gene-group p (4 genes):
//    Wg float4 + bias live in REGISTERS, warp loops over a 256-row b-chunk,
//    8 LDG.128 in flight, 4 concurrent b-fronts.
// =============================================================================
__global__ void __launch_bounds__(256, 5) fused_kernel(
    const float* __restrict__ x,
    const float* __restrict__ z1, const float* __restrict__ z2,
    const float* __restrict__ z3,
    const float* __restrict__ Wg, const float* __restrict__ bg,
    const float* __restrict__ W1, const float* __restrict__ W2,
    const float* __restrict__ W3)
{
    const int bid = blockIdx.x;
    if (bid < NZBLK) {
        const int zc   = bid >> 4;            // 0..13
        const int row0 = (bid & 15) * 64;
        const float* A; const float* W; int lda, k0;
        if (zc < 8)       { A = z1; W = W1; lda = 4096; k0 = zc * 512; }
        else if (zc < 12) { A = z2; W = W2; lda = 2048; k0 = (zc - 8)  * 512; }
        else              { A = z3; W = W3; lda = 1024; k0 = (zc - 12) * 512; }
        gemm_body<true>(A, W, lda, k0, 512, NGC + zc, row0);
        return;
    }

    // ---- gene population: 2000 warp-tasks = 500 p-groups x 4 b-chunks ----
    const int lane = threadIdx.x & 31;
    const int w    = (bid - NZBLK) * 8 + (threadIdx.x >> 5);  // 0..1999
    const int p    = w >> 2;                 // gene group 0..499
    const int b0   = (w & 3) * 256;          // b-chunk of 256 rows

    // register-resident weights & bias for this warp's 4 genes
    const float4 wv  = *(const float4*)(Wg + (size_t)p * 128 + lane * 4);
    const int    g   = p * 4 + (lane >> 3);
    const float  bias = __ldg(bg + g);
    const bool   is_store_lane = (lane & 7) == 0;

    const float* xp = x + (size_t)b0 * ROWSTRIDE + (size_t)p * 128 + lane * 4;
    float* gp = g_gene + (size_t)b0 * G_ + g;

    for (int i = 0; i < 256; i += 8) {
        float4 xv[8];
        #pragma unroll
        for (int j = 0; j < 8; j++)
            xv[j] = __ldcs((const float4*)(xp + (size_t)(i + j) * ROWSTRIDE));

        float d[8];
        #pragma unroll
        for (int j = 0; j < 8; j++)
            d[j] = xv[j].x * wv.x + xv[j].y * wv.y + xv[j].z * wv.z + xv[j].w * wv.w;

        #pragma unroll
        for (int j = 0; j < 8; j++) {
            d[j] += __shfl_down_sync(0xffffffffu, d[j], 4);
            d[j] += __shfl_down_sync(0xffffffffu, d[j], 2);
            d[j] += __shfl_down_sync(0xffffffffu, d[j], 1);
        }
        if (is_store_lane) {
            #pragma unroll
            for (int j = 0; j < 8; j++)
                gp[(size_t)(i + j) * G_] = fmaxf(d[j] + bias, 0.0f);
        }
    }
}

// =============================================================================
// Gene-GEMM kernel: NGC chunks (K=100 each), 16 x 20 = 320 blocks (~2.2/SM).
// =============================================================================
__global__ void __launch_bounds__(256, 5) gene_gemm_kernel(const float* __restrict__ W0)
{
    const int c    = blockIdx.y;                  // 0..NGC-1
    const int row0 = blockIdx.x * 64;
    gemm_body<false>(g_gene, W0, G_, c * 100, 100, c, row0);
}

// =============================================================================
// Finish kernel: reduce split-K partials, fusion, final 64->64->64->1 MLP.
// =============================================================================
__global__ void __launch_bounds__(256) finish_kernel(
    const float* __restrict__ b0, const float* __restrict__ b1,
    const float* __restrict__ b2, const float* __restrict__ b3,
    const float* __restrict__ w1, const float* __restrict__ w2,
    const float* __restrict__ w3,
    const float* __restrict__ fW1, const float* __restrict__ fb1,
    const float* __restrict__ fW2, const float* __restrict__ fb2,
    const float* __restrict__ fW3, const float* __restrict__ fb3,
    float* __restrict__ out)
{
    __shared__ float sW1[64 * 64];
    __shared__ float sW2[64 * 64];
    __shared__ float sbuf[4][64];
    __shared__ float sred[8];

    const int t = threadIdx.x;
    const int h = t & 63;
    const int r = t >> 6;
    for (int i = t; i < 64 * 64; i += 256) { sW1[i] = fW1[i]; sW2[i] = fW2[i]; }

    const int b = blockIdx.x * 4 + r;

    float a0 = 0.f, a1 = 0.f, a2 = 0.f, a3 = 0.f;
    #pragma unroll
    for (int cc = 0;       cc < NGC;      cc++) a0 += g_part[((size_t)cc * B_ + b) * 64 + h];
    #pragma unroll
    for (int cc = NGC;     cc < NGC + 8;  cc++) a1 += g_part[((size_t)cc * B_ + b) * 64 + h];
    #pragma unroll
    for (int cc = NGC + 8; cc < NGC + 12; cc++) a2 += g_part[((size_t)cc * B_ + b) * 64 + h];
    #pragma unroll
    for (int cc = NGC + 12; cc < NGC + 14; cc++) a3 += g_part[((size_t)cc * B_ + b) * 64 + h];

    float d = fmaxf(a0 + b0[h], 0.f);
    d += fmaxf(a1 + b1[h], 0.f) * w1[h];
    d += fmaxf(a2 + b2[h], 0.f) * w2[h];
    d += fmaxf(a3 + b3[h], 0.f) * w3[h];

    __syncthreads();
    sbuf[r][h] = d;
    __syncthreads();
    float acc = fb1[h];
    #pragma unroll
    for (int k = 0; k < 64; k++) acc = fmaf(sbuf[r][k], sW1[k * 64 + h], acc);
    const float hv = fmaxf(acc, 0.f);
    __syncthreads();
    sbuf[r][h] = hv;
    __syncthreads();
    acc = fb2[h];
    #pragma unroll
    for (int k = 0; k < 64; k++) acc = fmaf(sbuf[r][k], sW2[k * 64 + h], acc);
    const float h2 = fmaxf(acc, 0.f);

    float val = h2 * fW3[h];
    #pragma unroll
    for (int off = 16; off; off >>= 1) val += __shfl_down_sync(0xffffffffu, val, off);
    if ((t & 31) == 0) sred[t >> 5] = val;
    __syncthreads();
    if (h == 0) out[b] = sred[2 * r] + sred[2 * r + 1] + fb3[0];
}

// =============================================================================
// Launcher (graph-capturable: 3 kernel launches, no sync, no alloc)
// =============================================================================
extern "C" void kernel_launch(void* const* d_in, const int* in_sizes, int n_in,
                              void* d_out, int out_size)
{
    const float* x   = (const float*)d_in[0];
    const float* z1  = (const float*)d_in[1];
    const float* z2  = (const float*)d_in[2];
    const float* z3  = (const float*)d_in[3];
    const float* Wg  = (const float*)d_in[4];
    const float* bg  = (const float*)d_in[5];
    const float* W0  = (const float*)d_in[6];
    const float* b0  = (const float*)d_in[7];
    const float* W1  = (const float*)d_in[8];
    const float* b1  = (const float*)d_in[9];
    const float* W2  = (const float*)d_in[10];
    const float* b2  = (const float*)d_in[11];
    const float* W3  = (const float*)d_in[12];
    const float* b3  = (const float*)d_in[13];
    const float* w1  = (const float*)d_in[14];
    const float* w2  = (const float*)d_in[15];
    const float* w3  = (const float*)d_in[16];
    const float* fW1 = (const float*)d_in[17];
    const float* fb1 = (const float*)d_in[18];
    const float* fW2 = (const float*)d_in[19];
    const float* fb2 = (const float*)d_in[20];
    const float* fW3 = (const float*)d_in[21];
    const float* fb3 = (const float*)d_in[22];
    float* out = (float*)d_out;

    fused_kernel<<<NZBLK + GENEBLK, 256>>>(x, z1, z2, z3, Wg, bg, W1, W2, W3);
    gene_gemm_kernel<<<dim3(B_ / 64, NGC), 256>>>(W0);
    finish_kernel<<<B_ / 4, 256>>>(b0, b1, b2, b3, w1, w2, w3,
                                   fW1, fb1, fW2, fb2, fW3, fb3, out);
}

// round 9
// speedup vs baseline: 1.2551x; 1.0106x over previous
#include <cuda_runtime.h>

#define B_  1024
#define G_  2000
#define S_  32
#define H_  64
#define NGC 20           // gene-GEMM split-K chunks (K=100 each)
#define NCHUNK (NGC + 14)   // + 8 (z1) + 4 (z2) + 2 (z3)
#define NZBLK  224       // 14 z-chunks * 16 row tiles
#define GENEBLK 250      // gene producers (R4 layout)
#define GGBLK   (16 * NGC)   // 320 gene-GEMM consumers
#define ROWSTRIDE (G_ * S_)  // 64000 floats per x row

// Scratch (static device globals — allocation-free per harness rules)
__device__ float g_gene[B_ * G_];            // 8 MB
__device__ float g_part[NCHUNK * B_ * H_];   // 8.9 MB
__device__ int   g_done = 0;                 // gene-producer completion counter

// ---------------- packed fp32x2 helpers (sm_103a full-rate FMA path) ----------
__device__ __forceinline__ unsigned long long dup2(float v) {
    unsigned long long r;
    asm("mov.b64 %0, {%1, %1};" : "=l"(r) : "f"(v));
    return r;
}
__device__ __forceinline__ void ffma2(unsigned long long& d,
                                      unsigned long long a, unsigned long long b) {
    asm("fma.rn.f32x2 %0, %1, %2, %0;" : "+l"(d) : "l"(a), "l"(b));
}
__device__ __forceinline__ float2 unpk(unsigned long long v) {
    float2 r;
    asm("mov.b64 {%0, %1}, %2;" : "=f"(r.x), "=f"(r.y) : "l"(v));
    return r;
}
__device__ __forceinline__ int ld_acq(const int* p) {
    int v;
    asm volatile("ld.acquire.gpu.b32 %0, [%1];" : "=r"(v) : "l"(p) : "memory");
    return v;
}

// =============================================================================
// GEMM body (single-buffered smem staging): one 64x64 output tile over a
// <=512-wide K chunk; deterministic partial into g_part[c].
// =============================================================================
template <bool STREAM_A>
__device__ __forceinline__ void gemm_body(const float* __restrict__ A,
                                          const float* __restrict__ W,
                                          int lda, int k0, int klen,
                                          int c, int row0)
{
    __shared__ float As[32][66];
    __shared__ float Bs[32 * 64];

    const float* Ab = A + (size_t)row0 * lda + k0;
    const float* Wb = W + (size_t)k0 * 64;

    const int t    = threadIdx.x;
    const int tx   = t & 15;
    const int ty   = t >> 4;
    const int arow = t >> 3;
    const int af4  = (t & 7) * 4;
    const int ksteps = (klen + 31) >> 5;

    unsigned long long acc[2][4];
    #pragma unroll
    for (int p = 0; p < 2; p++)
        #pragma unroll
        for (int q = 0; q < 4; q++) acc[p][q] = 0ull;

    for (int ks = 0; ks < ksteps; ks++) {
        const int kk = ks * 32;
        const int kg = kk + af4;

        float4 av[2];
        #pragma unroll
        for (int i = 0; i < 2; i++) {
            const float* ap = Ab + (size_t)(arow + 32 * i) * lda;
            float4 v;
            if (kg + 3 < klen) {
                v = STREAM_A ? __ldcs((const float4*)(ap + kg))
                             : *(const float4*)(ap + kg);
            } else {
                v.x = (kg + 0 < klen) ? ap[kg + 0] : 0.0f;
                v.y = (kg + 1 < klen) ? ap[kg + 1] : 0.0f;
                v.z = (kg + 2 < klen) ? ap[kg + 2] : 0.0f;
                v.w = (kg + 3 < klen) ? ap[kg + 3] : 0.0f;
            }
            av[i] = v;
        }
        float4 bv2[2];
        #pragma unroll
        for (int i = 0; i < 2; i++) {
            const int q  = t + 256 * i;
            const int kr = kk + (q >> 4);
            float4 v = make_float4(0.f, 0.f, 0.f, 0.f);
            if (kr < klen) v = *(const float4*)(Wb + (size_t)kr * 64 + (q & 15) * 4);
            bv2[i] = v;
        }

        __syncthreads();
        #pragma unroll
        for (int i = 0; i < 2; i++) {
            As[af4 + 0][arow + 32 * i] = av[i].x;
            As[af4 + 1][arow + 32 * i] = av[i].y;
            As[af4 + 2][arow + 32 * i] = av[i].z;
            As[af4 + 3][arow + 32 * i] = av[i].w;
        }
        *(float4*)(Bs + (size_t)t * 4)         = bv2[0];
        *(float4*)(Bs + (size_t)(t + 256) * 4) = bv2[1];
        __syncthreads();

        #pragma unroll
        for (int k = 0; k < 32; k++) {
            const unsigned long long A0 = *(const unsigned long long*)&As[k][ty * 4];
            const unsigned long long A1 = *(const unsigned long long*)&As[k][ty * 4 + 2];
            const float4 bv = *(const float4*)(Bs + k * 64 + tx * 4);
            const unsigned long long Bq0 = dup2(bv.x);
            const unsigned long long Bq1 = dup2(bv.y);
            const unsigned long long Bq2 = dup2(bv.z);
            const unsigned long long Bq3 = dup2(bv.w);
            ffma2(acc[0][0], A0, Bq0); ffma2(acc[1][0], A1, Bq0);
            ffma2(acc[0][1], A0, Bq1); ffma2(acc[1][1], A1, Bq1);
            ffma2(acc[0][2], A0, Bq2); ffma2(acc[1][2], A1, Bq2);
            ffma2(acc[0][3], A0, Bq3); ffma2(acc[1][3], A1, Bq3);
        }
    }

    float* outp = g_part + ((size_t)c * B_ + row0 + ty * 4) * 64 + tx * 4;
    #pragma unroll
    for (int p = 0; p < 2; p++) {
        const float2 u0 = unpk(acc[p][0]);
        const float2 u1 = unpk(acc[p][1]);
        const float2 u2 = unpk(acc[p][2]);
        const float2 u3 = unpk(acc[p][3]);
        *(float4*)(outp + (size_t)(2 * p) * 64)     = make_float4(u0.x, u1.x, u2.x, u3.x);
        *(float4*)(outp + (size_t)(2 * p + 1) * 64) = make_float4(u0.y, u1.y, u2.y, u3.y);
    }
}

// =============================================================================
// Mega kernel — three block populations, one launch:
//  [0, 224):    z-GEMM chunks (independent)
//  [224, 474):  gene producers (R4 layout: warp owns p-group, 256-row b-chunk;
//               Wg + bias register-resident; 8 LDG.128 in flight)
//               -> __threadfence + atomicAdd(g_done) per block
//  [474, 794):  gene-GEMM consumers: spin until g_done == GENEBLK, then
//               compute split-K chunk of gene @ W0.
// Producers occupy low bids -> all resident in wave 1 (474 < 740 capacity at
// 5 blocks/SM); consumer spin is deadlock-free. z-GEMM blocks free slots
// independently for any straggler blocks.
// =============================================================================
__global__ void __launch_bounds__(256, 5) mega_kernel(
    const float* __restrict__ x,
    const float* __restrict__ z1, const float* __restrict__ z2,
    const float* __restrict__ z3,
    const float* __restrict__ Wg, const float* __restrict__ bg,
    const float* __restrict__ W0, const float* __restrict__ W1,
    const float* __restrict__ W2, const float* __restrict__ W3)
{
    const int bid = blockIdx.x;
    if (bid < NZBLK) {
        const int zc   = bid >> 4;            // 0..13
        const int row0 = (bid & 15) * 64;
        const float* A; const float* W; int lda, k0;
        if (zc < 8)       { A = z1; W = W1; lda = 4096; k0 = zc * 512; }
        else if (zc < 12) { A = z2; W = W2; lda = 2048; k0 = (zc - 8)  * 512; }
        else              { A = z3; W = W3; lda = 1024; k0 = (zc - 12) * 512; }
        gemm_body<true>(A, W, lda, k0, 512, NGC + zc, row0);
        return;
    }

    if (bid < NZBLK + GENEBLK) {
        // ---- gene producers: 2000 warp-tasks = 500 p-groups x 4 b-chunks ----
        const int lane = threadIdx.x & 31;
        const int w    = (bid - NZBLK) * 8 + (threadIdx.x >> 5);  // 0..1999
        const int p    = w >> 2;                 // gene group 0..499
        const int b0   = (w & 3) * 256;          // b-chunk of 256 rows

        const float4 wv  = *(const float4*)(Wg + (size_t)p * 128 + lane * 4);
        const int    g   = p * 4 + (lane >> 3);
        const float  bias = __ldg(bg + g);
        const bool   is_store_lane = (lane & 7) == 0;

        const float* xp = x + (size_t)b0 * ROWSTRIDE + (size_t)p * 128 + lane * 4;
        float* gp = g_gene + (size_t)b0 * G_ + g;

        for (int i = 0; i < 256; i += 8) {
            float4 xv[8];
            #pragma unroll
            for (int j = 0; j < 8; j++)
                xv[j] = __ldcs((const float4*)(xp + (size_t)(i + j) * ROWSTRIDE));

            float d[8];
            #pragma unroll
            for (int j = 0; j < 8; j++)
                d[j] = xv[j].x * wv.x + xv[j].y * wv.y + xv[j].z * wv.z + xv[j].w * wv.w;

            #pragma unroll
            for (int j = 0; j < 8; j++) {
                d[j] += __shfl_down_sync(0xffffffffu, d[j], 4);
                d[j] += __shfl_down_sync(0xffffffffu, d[j], 2);
                d[j] += __shfl_down_sync(0xffffffffu, d[j], 1);
            }
            if (is_store_lane) {
                #pragma unroll
                for (int j = 0; j < 8; j++)
                    gp[(size_t)(i + j) * G_] = fmaxf(d[j] + bias, 0.0f);
            }
        }

        __syncthreads();
        __threadfence();
        if (threadIdx.x == 0) atomicAdd(&g_done, 1);
        return;
    }

    // ---- gene-GEMM consumers ----
    if (threadIdx.x == 0) {
        while (ld_acq(&g_done) < GENEBLK) __nanosleep(128);
    }
    __syncthreads();

    const int cb   = bid - (NZBLK + GENEBLK);   // 0..319
    const int c    = cb >> 4;                   // 0..NGC-1
    const int row0 = (cb & 15) * 64;
    gemm_body<false>(g_gene, W0, G_, c * 100, 100, c, row0);
}

// =============================================================================
// Finish kernel: reduce split-K partials, fusion, final 64->64->64->1 MLP.
// Also resets g_done for the next graph replay (deterministic).
// =============================================================================
__global__ void __launch_bounds__(256) finish_kernel(
    const float* __restrict__ b0, const float* __restrict__ b1,
    const float* __restrict__ b2, const float* __restrict__ b3,
    const float* __restrict__ w1, const float* __restrict__ w2,
    const float* __restrict__ w3,
    const float* __restrict__ fW1, const float* __restrict__ fb1,
    const float* __restrict__ fW2, const float* __restrict__ fb2,
    const float* __restrict__ fW3, const float* __restrict__ fb3,
    float* __restrict__ out)
{
    __shared__ float sW1[64 * 64];
    __shared__ float sW2[64 * 64];
    __shared__ float sbuf[4][64];
    __shared__ float sred[8];

    if (blockIdx.x == 0 && threadIdx.x == 0) g_done = 0;   // reset for next replay

    const int t = threadIdx.x;
    const int h = t & 63;
    const int r = t >> 6;
    for (int i = t; i < 64 * 64; i += 256) { sW1[i] = fW1[i]; sW2[i] = fW2[i]; }

    const int b = blockIdx.x * 4 + r;

    float a0 = 0.f, a1 = 0.f, a2 = 0.f, a3 = 0.f;
    #pragma unroll
    for (int cc = 0;       cc < NGC;      cc++) a0 += g_part[((size_t)cc * B_ + b) * 64 + h];
    #pragma unroll
    for (int cc = NGC;     cc < NGC + 8;  cc++) a1 += g_part[((size_t)cc * B_ + b) * 64 + h];
    #pragma unroll
    for (int cc = NGC + 8; cc < NGC + 12; cc++) a2 += g_part[((size_t)cc * B_ + b) * 64 + h];
    #pragma unroll
    for (int cc = NGC + 12; cc < NGC + 14; cc++) a3 += g_part[((size_t)cc * B_ + b) * 64 + h];

    float d = fmaxf(a0 + b0[h], 0.f);
    d += fmaxf(a1 + b1[h], 0.f) * w1[h];
    d += fmaxf(a2 + b2[h], 0.f) * w2[h];
    d += fmaxf(a3 + b3[h], 0.f) * w3[h];

    __syncthreads();
    sbuf[r][h] = d;
    __syncthreads();
    float acc = fb1[h];
    #pragma unroll
    for (int k = 0; k < 64; k++) acc = fmaf(sbuf[r][k], sW1[k * 64 + h], acc);
    const float hv = fmaxf(acc, 0.f);
    __syncthreads();
    sbuf[r][h] = hv;
    __syncthreads();
    acc = fb2[h];
    #pragma unroll
    for (int k = 0; k < 64; k++) acc = fmaf(sbuf[r][k], sW2[k * 64 + h], acc);
    const float h2 = fmaxf(acc, 0.f);

    float val = h2 * fW3[h];
    #pragma unroll
    for (int off = 16; off; off >>= 1) val += __shfl_down_sync(0xffffffffu, val, off);
    if ((t & 31) == 0) sred[t >> 5] = val;
    __syncthreads();
    if (h == 0) out[b] = sred[2 * r] + sred[2 * r + 1] + fb3[0];
}

// =============================================================================
// Launcher (graph-capturable: 2 kernel launches, no sync, no alloc)
// =============================================================================
extern "C" void kernel_launch(void* const* d_in, const int* in_sizes, int n_in,
                              void* d_out, int out_size)
{
    const float* x   = (const float*)d_in[0];
    const float* z1  = (const float*)d_in[1];
    const float* z2  = (const float*)d_in[2];
    const float* z3  = (const float*)d_in[3];
    const float* Wg  = (const float*)d_in[4];
    const float* bg  = (const float*)d_in[5];
    const float* W0  = (const float*)d_in[6];
    const float* b0  = (const float*)d_in[7];
    const float* W1  = (const float*)d_in[8];
    const float* b1  = (const float*)d_in[9];
    const float* W2  = (const float*)d_in[10];
    const float* b2  = (const float*)d_in[11];
    const float* W3  = (const float*)d_in[12];
    const float* b3  = (const float*)d_in[13];
    const float* w1  = (const float*)d_in[14];
    const float* w2  = (const float*)d_in[15];
    const float* w3  = (const float*)d_in[16];
    const float* fW1 = (const float*)d_in[17];
    const float* fb1 = (const float*)d_in[18];
    const float* fW2 = (const float*)d_in[19];
    const float* fb2 = (const float*)d_in[20];
    const float* fW3 = (const float*)d_in[21];
    const float* fb3 = (const float*)d_in[22];
    float* out = (float*)d_out;

    mega_kernel<<<NZBLK + GENEBLK + GGBLK, 256>>>(x, z1, z2, z3, Wg, bg,
                                                  W0, W1, W2, W3);
    finish_kernel<<<B_ / 4, 256>>>(b0, b1, b2, b3, w1, w2, w3,
                                   fW1, fb1, fW2, fb2, fW3, fb3, out);
}

// round 10
// speedup vs baseline: 1.2822x; 1.0216x over previous
#include <cuda_runtime.h>

#define B_  1024
#define G_  2000
#define S_  32
#define H_  64
#define NGC 20              // gene-GEMM split-K chunks (K=100 each)
#define NCHUNK (NGC + 14)   // + 8 (z1) + 4 (z2) + 2 (z3)
#define NZBLK  224          // 14 z-chunks * 16 row tiles
#define GENEBLK 250         // gene producers (R4 layout)
#define GGBLK   (16 * NGC)  // 320 gene-GEMM consumers
#define FINBLK  256         // finish blocks (4 rows each)
#define PDONE_TARGET (NZBLK + GGBLK)   // 544 g_part writers
#define ROWSTRIDE (G_ * S_)  // 64000 floats per x row

// Scratch (static device globals — allocation-free per harness rules)
__device__ float g_gene[B_ * G_];            // 8 MB
__device__ float g_part[NCHUNK * B_ * H_];   // 8.9 MB
__device__ int   g_done  = 0;                // gene-producer counter (250)
__device__ int   g_pdone = 0;                // g_part-writer counter (544)
__device__ int   g_fin   = 0;                // finish-block counter (256)

// ---------------- packed fp32x2 helpers (sm_103a full-rate FMA path) ----------
__device__ __forceinline__ unsigned long long dup2(float v) {
    unsigned long long r;
    asm("mov.b64 %0, {%1, %1};" : "=l"(r) : "f"(v));
    return r;
}
__device__ __forceinline__ void ffma2(unsigned long long& d,
                                      unsigned long long a, unsigned long long b) {
    asm("fma.rn.f32x2 %0, %1, %2, %0;" : "+l"(d) : "l"(a), "l"(b));
}
__device__ __forceinline__ float2 unpk(unsigned long long v) {
    float2 r;
    asm("mov.b64 {%0, %1}, %2;" : "=f"(r.x), "=f"(r.y) : "l"(v));
    return r;
}
__device__ __forceinline__ int ld_acq(const int* p) {
    int v;
    asm volatile("ld.acquire.gpu.b32 %0, [%1];" : "=r"(v) : "l"(p) : "memory");
    return v;
}

// =============================================================================
// GEMM body (smem passed in): one 64x64 output tile over a <=512-wide K chunk;
// deterministic partial into g_part[c].
// =============================================================================
template <bool STREAM_A>
__device__ __forceinline__ void gemm_body(float* __restrict__ As,   // 32*66 floats
                                          float* __restrict__ Bs,   // 32*64 floats
                                          const float* __restrict__ A,
                                          const float* __restrict__ W,
                                          int lda, int k0, int klen,
                                          int c, int row0)
{
    const float* Ab = A + (size_t)row0 * lda + k0;
    const float* Wb = W + (size_t)k0 * 64;

    const int t    = threadIdx.x;
    const int tx   = t & 15;
    const int ty   = t >> 4;
    const int arow = t >> 3;
    const int af4  = (t & 7) * 4;
    const int ksteps = (klen + 31) >> 5;

    unsigned long long acc[2][4];
    #pragma unroll
    for (int p = 0; p < 2; p++)
        #pragma unroll
        for (int q = 0; q < 4; q++) acc[p][q] = 0ull;

    for (int ks = 0; ks < ksteps; ks++) {
        const int kk = ks * 32;
        const int kg = kk + af4;

        float4 av[2];
        #pragma unroll
        for (int i = 0; i < 2; i++) {
            const float* ap = Ab + (size_t)(arow + 32 * i) * lda;
            float4 v;
            if (kg + 3 < klen) {
                v = STREAM_A ? __ldcs((const float4*)(ap + kg))
                             : *(const float4*)(ap + kg);
            } else {
                v.x = (kg + 0 < klen) ? ap[kg + 0] : 0.0f;
                v.y = (kg + 1 < klen) ? ap[kg + 1] : 0.0f;
                v.z = (kg + 2 < klen) ? ap[kg + 2] : 0.0f;
                v.w = (kg + 3 < klen) ? ap[kg + 3] : 0.0f;
            }
            av[i] = v;
        }
        float4 bv2[2];
        #pragma unroll
        for (int i = 0; i < 2; i++) {
            const int q  = t + 256 * i;
            const int kr = kk + (q >> 4);
            float4 v = make_float4(0.f, 0.f, 0.f, 0.f);
            if (kr < klen) v = *(const float4*)(Wb + (size_t)kr * 64 + (q & 15) * 4);
            bv2[i] = v;
        }

        __syncthreads();
        #pragma unroll
        for (int i = 0; i < 2; i++) {
            As[(af4 + 0) * 66 + arow + 32 * i] = av[i].x;
            As[(af4 + 1) * 66 + arow + 32 * i] = av[i].y;
            As[(af4 + 2) * 66 + arow + 32 * i] = av[i].z;
            As[(af4 + 3) * 66 + arow + 32 * i] = av[i].w;
        }
        *(float4*)(Bs + (size_t)t * 4)         = bv2[0];
        *(float4*)(Bs + (size_t)(t + 256) * 4) = bv2[1];
        __syncthreads();

        #pragma unroll
        for (int k = 0; k < 32; k++) {
            const unsigned long long A0 = *(const unsigned long long*)&As[k * 66 + ty * 4];
            const unsigned long long A1 = *(const unsigned long long*)&As[k * 66 + ty * 4 + 2];
            const float4 bv = *(const float4*)(Bs + k * 64 + tx * 4);
            const unsigned long long Bq0 = dup2(bv.x);
            const unsigned long long Bq1 = dup2(bv.y);
            const unsigned long long Bq2 = dup2(bv.z);
            const unsigned long long Bq3 = dup2(bv.w);
            ffma2(acc[0][0], A0, Bq0); ffma2(acc[1][0], A1, Bq0);
            ffma2(acc[0][1], A0, Bq1); ffma2(acc[1][1], A1, Bq1);
            ffma2(acc[0][2], A0, Bq2); ffma2(acc[1][2], A1, Bq2);
            ffma2(acc[0][3], A0, Bq3); ffma2(acc[1][3], A1, Bq3);
        }
    }

    float* outp = g_part + ((size_t)c * B_ + row0 + ty * 4) * 64 + tx * 4;
    #pragma unroll
    for (int p = 0; p < 2; p++) {
        const float2 u0 = unpk(acc[p][0]);
        const float2 u1 = unpk(acc[p][1]);
        const float2 u2 = unpk(acc[p][2]);
        const float2 u3 = unpk(acc[p][3]);
        *(float4*)(outp + (size_t)(2 * p) * 64)     = make_float4(u0.x, u1.x, u2.x, u3.x);
        *(float4*)(outp + (size_t)(2 * p + 1) * 64) = make_float4(u0.y, u1.y, u2.y, u3.y);
    }
}

// =============================================================================
// Mega kernel — four block populations, ONE launch:
//  [0, 224):     z-GEMM chunks                    -> fence + g_pdone++
//  [224, 474):   gene producers (R4 layout)       -> fence + g_done++
//  [474, 794):   gene-GEMM consumers: spin g_done==250, gemm -> fence+g_pdone++
//  [794, 1050):  finish: PRE-STAGE fW1/fW2 in smem, spin g_pdone==544,
//                reduce partials + fusion + MLP -> out. Last block resets ctrs.
// Producers hold low bids -> resident in wave 1; spinners never starve them.
// =============================================================================
__global__ void __launch_bounds__(256, 5) mega_kernel(
    const float* __restrict__ x,
    const float* __restrict__ z1, const float* __restrict__ z2,
    const float* __restrict__ z3,
    const float* __restrict__ Wg, const float* __restrict__ bg,
    const float* __restrict__ W0, const float* __restrict__ b0,
    const float* __restrict__ W1, const float* __restrict__ b1,
    const float* __restrict__ W2, const float* __restrict__ b2,
    const float* __restrict__ W3, const float* __restrict__ b3,
    const float* __restrict__ w1, const float* __restrict__ w2,
    const float* __restrict__ w3,
    const float* __restrict__ fW1, const float* __restrict__ fb1,
    const float* __restrict__ fW2, const float* __restrict__ fb2,
    const float* __restrict__ fW3, const float* __restrict__ fb3,
    float* __restrict__ out)
{
    __shared__ __align__(128) float pool[8456];   // max(GEMM 4160, finish 8456) floats

    const int bid = blockIdx.x;
    const int t   = threadIdx.x;

    if (bid < NZBLK) {
        const int zc   = bid >> 4;            // 0..13
        const int row0 = (bid & 15) * 64;
        const float* A; const float* W; int lda, k0;
        if (zc < 8)       { A = z1; W = W1; lda = 4096; k0 = zc * 512; }
        else if (zc < 12) { A = z2; W = W2; lda = 2048; k0 = (zc - 8)  * 512; }
        else              { A = z3; W = W3; lda = 1024; k0 = (zc - 12) * 512; }
        gemm_body<true>(pool, pool + 2112, A, W, lda, k0, 512, NGC + zc, row0);
        __syncthreads();
        __threadfence();
        if (t == 0) atomicAdd(&g_pdone, 1);
        return;
    }

    if (bid < NZBLK + GENEBLK) {
        // ---- gene producers: 2000 warp-tasks = 500 p-groups x 4 b-chunks ----
        const int lane = t & 31;
        const int w    = (bid - NZBLK) * 8 + (t >> 5);   // 0..1999
        const int p    = w >> 2;                 // gene group 0..499
        const int b0r  = (w & 3) * 256;          // b-chunk of 256 rows

        const float4 wv  = *(const float4*)(Wg + (size_t)p * 128 + lane * 4);
        const int    g   = p * 4 + (lane >> 3);
        const float  bias = __ldg(bg + g);
        const bool   is_store_lane = (lane & 7) == 0;

        const float* xp = x + (size_t)b0r * ROWSTRIDE + (size_t)p * 128 + lane * 4;
        float* gp = g_gene + (size_t)b0r * G_ + g;

        for (int i = 0; i < 256; i += 8) {
            float4 xv[8];
            #pragma unroll
            for (int j = 0; j < 8; j++)
                xv[j] = __ldcs((const float4*)(xp + (size_t)(i + j) * ROWSTRIDE));

            float d[8];
            #pragma unroll
            for (int j = 0; j < 8; j++)
                d[j] = xv[j].x * wv.x + xv[j].y * wv.y + xv[j].z * wv.z + xv[j].w * wv.w;

            #pragma unroll
            for (int j = 0; j < 8; j++) {
                d[j] += __shfl_down_sync(0xffffffffu, d[j], 4);
                d[j] += __shfl_down_sync(0xffffffffu, d[j], 2);
                d[j] += __shfl_down_sync(0xffffffffu, d[j], 1);
            }
            if (is_store_lane) {
                #pragma unroll
                for (int j = 0; j < 8; j++)
                    gp[(size_t)(i + j) * G_] = fmaxf(d[j] + bias, 0.0f);
            }
        }

        __syncthreads();
        __threadfence();
        if (t == 0) atomicAdd(&g_done, 1);
        return;
    }

    if (bid < NZBLK + GENEBLK + GGBLK) {
        // ---- gene-GEMM consumers ----
        if (t == 0) {
            while (ld_acq(&g_done) < GENEBLK) __nanosleep(128);
        }
        __syncthreads();

        const int cb   = bid - (NZBLK + GENEBLK);   // 0..319
        const int c    = cb >> 4;                   // 0..NGC-1
        const int row0 = (cb & 15) * 64;
        gemm_body<false>(pool, pool + 2112, g_gene, W0, G_, c * 100, 100, c, row0);
        __syncthreads();
        __threadfence();
        if (t == 0) atomicAdd(&g_pdone, 1);
        return;
    }

    // ---- finish population ----
    float* sW1 = pool;                 // 4096
    float* sW2 = pool + 4096;          // 4096
    float (*sbuf)[64] = (float(*)[64])(pool + 8192);   // 4*64
    float* sred = pool + 8192 + 256;   // 8

    const int h = t & 63;
    const int r = t >> 6;

    // PRE-STAGE weights while producers still run (overlaps ~10us of latency)
    #pragma unroll
    for (int i = 0; i < 4; i++) {
        ((float4*)sW1)[t + 256 * i] = ((const float4*)fW1)[t + 256 * i];
        ((float4*)sW2)[t + 256 * i] = ((const float4*)fW2)[t + 256 * i];
    }

    if (t == 0) {
        while (ld_acq(&g_pdone) < PDONE_TARGET) __nanosleep(128);
    }
    __syncthreads();   // gate + weight-staging visibility

    const int b = (bid - (NZBLK + GENEBLK + GGBLK)) * 4 + r;

    float a0 = 0.f, a1 = 0.f, a2 = 0.f, a3 = 0.f;
    #pragma unroll
    for (int cc = 0;       cc < NGC;      cc++) a0 += g_part[((size_t)cc * B_ + b) * 64 + h];
    #pragma unroll
    for (int cc = NGC;     cc < NGC + 8;  cc++) a1 += g_part[((size_t)cc * B_ + b) * 64 + h];
    #pragma unroll
    for (int cc = NGC + 8; cc < NGC + 12; cc++) a2 += g_part[((size_t)cc * B_ + b) * 64 + h];
    #pragma unroll
    for (int cc = NGC + 12; cc < NGC + 14; cc++) a3 += g_part[((size_t)cc * B_ + b) * 64 + h];

    float d = fmaxf(a0 + b0[h], 0.f);
    d += fmaxf(a1 + b1[h], 0.f) * w1[h];
    d += fmaxf(a2 + b2[h], 0.f) * w2[h];
    d += fmaxf(a3 + b3[h], 0.f) * w3[h];

    sbuf[r][h] = d;
    __syncthreads();
    float acc = fb1[h];
    #pragma unroll
    for (int k = 0; k < 64; k++) acc = fmaf(sbuf[r][k], sW1[k * 64 + h], acc);
    const float hv = fmaxf(acc, 0.f);
    __syncthreads();
    sbuf[r][h] = hv;
    __syncthreads();
    acc = fb2[h];
    #pragma unroll
    for (int k = 0; k < 64; k++) acc = fmaf(sbuf[r][k], sW2[k * 64 + h], acc);
    const float h2 = fmaxf(acc, 0.f);

    float val = h2 * fW3[h];
    #pragma unroll
    for (int off = 16; off; off >>= 1) val += __shfl_down_sync(0xffffffffu, val, off);
    if ((t & 31) == 0) sred[t >> 5] = val;
    __syncthreads();
    if (h == 0) out[b] = sred[2 * r] + sred[2 * r + 1] + fb3[0];

    // Counter reset: last finish block (all finish blocks have passed the gate
    // by the time the last one increments) -> safe, deterministic across replays.
    __syncthreads();
    if (t == 0) {
        const int o = atomicAdd(&g_fin, 1);
        if (o == FINBLK - 1) {
            atomicExch(&g_done, 0);
            atomicExch(&g_pdone, 0);
            atomicExch(&g_fin, 0);
        }
    }
}

// =============================================================================
// Launcher (graph-capturable: ONE kernel launch, no sync, no alloc)
// =============================================================================
extern "C" void kernel_launch(void* const* d_in, const int* in_sizes, int n_in,
                              void* d_out, int out_size)
{
    const float* x   = (const float*)d_in[0];
    const float* z1  = (const float*)d_in[1];
    const float* z2  = (const float*)d_in[2];
    const float* z3  = (const float*)d_in[3];
    const float* Wg  = (const float*)d_in[4];
    const float* bg  = (const float*)d_in[5];
    const float* W0  = (const float*)d_in[6];
    const float* b0  = (const float*)d_in[7];
    const float* W1  = (const float*)d_in[8];
    const float* b1  = (const float*)d_in[9];
    const float* W2  = (const float*)d_in[10];
    const float* b2  = (const float*)d_in[11];
    const float* W3  = (const float*)d_in[12];
    const float* b3  = (const float*)d_in[13];
    const float* w1  = (const float*)d_in[14];
    const float* w2  = (const float*)d_in[15];
    const float* w3  = (const float*)d_in[16];
    const float* fW1 = (const float*)d_in[17];
    const float* fb1 = (const float*)d_in[18];
    const float* fW2 = (const float*)d_in[19];
    const float* fb2 = (const float*)d_in[20];
    const float* fW3 = (const float*)d_in[21];
    const float* fb3 = (const float*)d_in[22];
    float* out = (float*)d_out;

    mega_kernel<<<NZBLK + GENEBLK + GGBLK + FINBLK, 256>>>(
        x, z1, z2, z3, Wg, bg, W0, b0, W1, b1, W2, b2, W3, b3,
        w1, w2, w3, fW1, fb1, fW2, fb2, fW3, fb3, out);
}

// round 11
// speedup vs baseline: 1.3515x; 1.0540x over previous
#include <cuda_runtime.h>

#define B_  1024
#define G_  2000
#define S_  32
#define H_  64
#define NGC 20              // gene-GEMM split-K chunks (K=100 each)
#define NCHUNK (NGC + 14)   // + 8 (z1) + 4 (z2) + 2 (z3)
#define NZBLK  224          // 14 z-chunks * 16 row tiles
#define GENEBLK 250         // gene producers (R4 layout)
#define GGBLK   (16 * NGC)  // 320 gene-GEMM consumers
#define FINBLK  128         // finish blocks (8 rows each)
#define CHUNK_TGT 13        // producer blocks covering one gene-GEMM chunk
#define PDONE_TARGET (NZBLK + GGBLK)   // 544 g_part writers
#define ROWSTRIDE (G_ * S_)  // 64000 floats per x row

// Scratch (static device globals — allocation-free per harness rules)
__device__ float g_gene[B_ * G_];            // 8 MB
__device__ float g_part[NCHUNK * B_ * H_];   // 8.9 MB
__device__ int   g_cdone[NGC];               // per-chunk producer counters
__device__ int   g_pdone = 0;                // g_part-writer counter (544)
__device__ int   g_fin   = 0;                // finish-block counter (128)

// ---------------- packed fp32x2 helpers (sm_103a full-rate FMA path) ----------
__device__ __forceinline__ unsigned long long dup2(float v) {
    unsigned long long r;
    asm("mov.b64 %0, {%1, %1};" : "=l"(r) : "f"(v));
    return r;
}
__device__ __forceinline__ void ffma2(unsigned long long& d,
                                      unsigned long long a, unsigned long long b) {
    asm("fma.rn.f32x2 %0, %1, %2, %0;" : "+l"(d) : "l"(a), "l"(b));
}
__device__ __forceinline__ float2 unpk(unsigned long long v) {
    float2 r;
    asm("mov.b64 {%0, %1}, %2;" : "=f"(r.x), "=f"(r.y) : "l"(v));
    return r;
}
__device__ __forceinline__ int ld_acq(const int* p) {
    int v;
    asm volatile("ld.acquire.gpu.b32 %0, [%1];" : "=r"(v) : "l"(p) : "memory");
    return v;
}

// =============================================================================
// GEMM body (smem passed in): one 64x64 output tile over a <=512-wide K chunk;
// deterministic partial into g_part[c].
// =============================================================================
template <bool STREAM_A>
__device__ __forceinline__ void gemm_body(float* __restrict__ As,   // 32*66 floats
                                          float* __restrict__ Bs,   // 32*64 floats
                                          const float* __restrict__ A,
                                          const float* __restrict__ W,
                                          int lda, int k0, int klen,
                                          int c, int row0)
{
    const float* Ab = A + (size_t)row0 * lda + k0;
    const float* Wb = W + (size_t)k0 * 64;

    const int t    = threadIdx.x;
    const int tx   = t & 15;
    const int ty   = t >> 4;
    const int arow = t >> 3;
    const int af4  = (t & 7) * 4;
    const int ksteps = (klen + 31) >> 5;

    unsigned long long acc[2][4];
    #pragma unroll
    for (int p = 0; p < 2; p++)
        #pragma unroll
        for (int q = 0; q < 4; q++) acc[p][q] = 0ull;

    for (int ks = 0; ks < ksteps; ks++) {
        const int kk = ks * 32;
        const int kg = kk + af4;

        float4 av[2];
        #pragma unroll
        for (int i = 0; i < 2; i++) {
            const float* ap = Ab + (size_t)(arow + 32 * i) * lda;
            float4 v;
            if (kg + 3 < klen) {
                v = STREAM_A ? __ldcs((const float4*)(ap + kg))
                             : *(const float4*)(ap + kg);
            } else {
                v.x = (kg + 0 < klen) ? ap[kg + 0] : 0.0f;
                v.y = (kg + 1 < klen) ? ap[kg + 1] : 0.0f;
                v.z = (kg + 2 < klen) ? ap[kg + 2] : 0.0f;
                v.w = (kg + 3 < klen) ? ap[kg + 3] : 0.0f;
            }
            av[i] = v;
        }
        float4 bv2[2];
        #pragma unroll
        for (int i = 0; i < 2; i++) {
            const int q  = t + 256 * i;
            const int kr = kk + (q >> 4);
            float4 v = make_float4(0.f, 0.f, 0.f, 0.f);
            if (kr < klen) v = *(const float4*)(Wb + (size_t)kr * 64 + (q & 15) * 4);
            bv2[i] = v;
        }

        __syncthreads();
        #pragma unroll
        for (int i = 0; i < 2; i++) {
            As[(af4 + 0) * 66 + arow + 32 * i] = av[i].x;
            As[(af4 + 1) * 66 + arow + 32 * i] = av[i].y;
            As[(af4 + 2) * 66 + arow + 32 * i] = av[i].z;
            As[(af4 + 3) * 66 + arow + 32 * i] = av[i].w;
        }
        *(float4*)(Bs + (size_t)t * 4)         = bv2[0];
        *(float4*)(Bs + (size_t)(t + 256) * 4) = bv2[1];
        __syncthreads();

        #pragma unroll
        for (int k = 0; k < 32; k++) {
            const unsigned long long A0 = *(const unsigned long long*)&As[k * 66 + ty * 4];
            const unsigned long long A1 = *(const unsigned long long*)&As[k * 66 + ty * 4 + 2];
            const float4 bv = *(const float4*)(Bs + k * 64 + tx * 4);
            const unsigned long long Bq0 = dup2(bv.x);
            const unsigned long long Bq1 = dup2(bv.y);
            const unsigned long long Bq2 = dup2(bv.z);
            const unsigned long long Bq3 = dup2(bv.w);
            ffma2(acc[0][0], A0, Bq0); ffma2(acc[1][0], A1, Bq0);
            ffma2(acc[0][1], A0, Bq1); ffma2(acc[1][1], A1, Bq1);
            ffma2(acc[0][2], A0, Bq2); ffma2(acc[1][2], A1, Bq2);
            ffma2(acc[0][3], A0, Bq3); ffma2(acc[1][3], A1, Bq3);
        }
    }

    float* outp = g_part + ((size_t)c * B_ + row0 + ty * 4) * 64 + tx * 4;
    #pragma unroll
    for (int p = 0; p < 2; p++) {
        const float2 u0 = unpk(acc[p][0]);
        const float2 u1 = unpk(acc[p][1]);
        const float2 u2 = unpk(acc[p][2]);
        const float2 u3 = unpk(acc[p][3]);
        *(float4*)(outp + (size_t)(2 * p) * 64)     = make_float4(u0.x, u1.x, u2.x, u3.x);
        *(float4*)(outp + (size_t)(2 * p + 1) * 64) = make_float4(u0.y, u1.y, u2.y, u3.y);
    }
}

// =============================================================================
// Mega kernel — four block populations, ONE launch:
//  [0, 224):    z-GEMM chunks                      -> fence + g_pdone++
//  [224, 474):  gene producers (block completes p-groups {2gb, 2gb+1})
//               -> fence + g_cdone[chunk(s)]++   (fine-grained gating)
//  [474, 794):  gene-GEMM consumers: spin g_cdone[c] == 13, gemm
//               -> fence + g_pdone++
//  [794, 922):  finish (8 rows/block): PRE-STAGE fW1/fW2, spin g_pdone==544,
//               reduce partials + fusion + MLP -> out. Last block resets ctrs.
// Producers hold low bids -> resident in wave 1; spinners never starve them.
// =============================================================================
__global__ void __launch_bounds__(256, 5) mega_kernel(
    const float* __restrict__ x,
    const float* __restrict__ z1, const float* __restrict__ z2,
    const float* __restrict__ z3,
    const float* __restrict__ Wg, const float* __restrict__ bg,
    const float* __restrict__ W0, const float* __restrict__ b0,
    const float* __restrict__ W1, const float* __restrict__ b1,
    const float* __restrict__ W2, const float* __restrict__ b2,
    const float* __restrict__ W3, const float* __restrict__ b3,
    const float* __restrict__ w1, const float* __restrict__ w2,
    const float* __restrict__ w3,
    const float* __restrict__ fW1, const float* __restrict__ fb1,
    const float* __restrict__ fW2, const float* __restrict__ fb2,
    const float* __restrict__ fW3, const float* __restrict__ fb3,
    float* __restrict__ out)
{
    __shared__ __align__(128) float pool[8720];   // max(GEMM 4160, finish 8720)

    const int bid = blockIdx.x;
    const int t   = threadIdx.x;

    if (bid < NZBLK) {
        const int zc   = bid >> 4;            // 0..13
        const int row0 = (bid & 15) * 64;
        const float* A; const float* W; int lda, k0;
        if (zc < 8)       { A = z1; W = W1; lda = 4096; k0 = zc * 512; }
        else if (zc < 12) { A = z2; W = W2; lda = 2048; k0 = (zc - 8)  * 512; }
        else              { A = z3; W = W3; lda = 1024; k0 = (zc - 12) * 512; }
        gemm_body<true>(pool, pool + 2112, A, W, lda, k0, 512, NGC + zc, row0);
        __syncthreads();
        __threadfence();
        if (t == 0) atomicAdd(&g_pdone, 1);
        return;
    }

    if (bid < NZBLK + GENEBLK) {
        // ---- gene producers: 2000 warp-tasks = 500 p-groups x 4 b-chunks ----
        const int gb   = bid - NZBLK;            // 0..249
        const int lane = t & 31;
        const int w    = gb * 8 + (t >> 5);      // 0..1999
        const int p    = w >> 2;                 // gene group 0..499
        const int b0r  = (w & 3) * 256;          // b-chunk of 256 rows

        const float4 wv  = *(const float4*)(Wg + (size_t)p * 128 + lane * 4);
        const int    g   = p * 4 + (lane >> 3);
        const float  bias = __ldg(bg + g);
        const bool   is_store_lane = (lane & 7) == 0;

        const float* xp = x + (size_t)b0r * ROWSTRIDE + (size_t)p * 128 + lane * 4;
        float* gp = g_gene + (size_t)b0r * G_ + g;

        for (int i = 0; i < 256; i += 8) {
            float4 xv[8];
            #pragma unroll
            for (int j = 0; j < 8; j++)
                xv[j] = __ldcs((const float4*)(xp + (size_t)(i + j) * ROWSTRIDE));

            float d[8];
            #pragma unroll
            for (int j = 0; j < 8; j++)
                d[j] = xv[j].x * wv.x + xv[j].y * wv.y + xv[j].z * wv.z + xv[j].w * wv.w;

            #pragma unroll
            for (int j = 0; j < 8; j++) {
                d[j] += __shfl_down_sync(0xffffffffu, d[j], 4);
                d[j] += __shfl_down_sync(0xffffffffu, d[j], 2);
                d[j] += __shfl_down_sync(0xffffffffu, d[j], 1);
            }
            if (is_store_lane) {
                #pragma unroll
                for (int j = 0; j < 8; j++)
                    gp[(size_t)(i + j) * G_] = fmaxf(d[j] + bias, 0.0f);
            }
        }

        __syncthreads();
        __threadfence();
        if (t == 0) {
            // block gb fully produced p-groups 2gb and 2gb+1
            const int ca = (2 * gb) / 25;        // 25 p-groups per chunk
            const int cb2 = (2 * gb + 1) / 25;
            atomicAdd(&g_cdone[ca], 1);
            if (cb2 != ca) atomicAdd(&g_cdone[cb2], 1);
        }
        return;
    }

    if (bid < NZBLK + GENEBLK + GGBLK) {
        // ---- gene-GEMM consumers: per-chunk gate ----
        const int cb   = bid - (NZBLK + GENEBLK);   // 0..319
        const int c    = cb >> 4;                   // 0..NGC-1
        const int row0 = (cb & 15) * 64;
        if (t == 0) {
            while (ld_acq(&g_cdone[c]) < CHUNK_TGT) __nanosleep(128);
        }
        __syncthreads();

        gemm_body<false>(pool, pool + 2112, g_gene, W0, G_, c * 100, 100, c, row0);
        __syncthreads();
        __threadfence();
        if (t == 0) atomicAdd(&g_pdone, 1);
        return;
    }

    // ---- finish population: 128 blocks x 8 rows ----
    float* sW1 = pool;                                   // 4096
    float* sW2 = pool + 4096;                            // 4096
    float (*sbuf)[64] = (float(*)[64])(pool + 8192);     // 8*64
    float* sred = pool + 8192 + 512;                     // 16

    const int h   = t & 63;
    const int r   = t >> 6;       // slot 0..3; thread handles rows r and r+4
    const int wid = t >> 5;

    // PRE-STAGE weights while producers still run
    #pragma unroll
    for (int i = 0; i < 4; i++) {
        ((float4*)sW1)[t + 256 * i] = ((const float4*)fW1)[t + 256 * i];
        ((float4*)sW2)[t + 256 * i] = ((const float4*)fW2)[t + 256 * i];
    }

    if (t == 0) {
        while (ld_acq(&g_pdone) < PDONE_TARGET) __nanosleep(128);
    }
    __syncthreads();   // gate + weight-staging visibility

    const int fb  = bid - (NZBLK + GENEBLK + GGBLK);
    const int b0r = fb * 8;

    float dd[2];
    #pragma unroll
    for (int rr = 0; rr < 2; rr++) {
        const int b = b0r + r + rr * 4;
        float a0 = 0.f, a1 = 0.f, a2 = 0.f, a3 = 0.f;
        #pragma unroll
        for (int cc = 0;       cc < NGC;      cc++) a0 += g_part[((size_t)cc * B_ + b) * 64 + h];
        #pragma unroll
        for (int cc = NGC;     cc < NGC + 8;  cc++) a1 += g_part[((size_t)cc * B_ + b) * 64 + h];
        #pragma unroll
        for (int cc = NGC + 8; cc < NGC + 12; cc++) a2 += g_part[((size_t)cc * B_ + b) * 64 + h];
        #pragma unroll
        for (int cc = NGC + 12; cc < NGC + 14; cc++) a3 += g_part[((size_t)cc * B_ + b) * 64 + h];

        float d = fmaxf(a0 + b0[h], 0.f);
        d += fmaxf(a1 + b1[h], 0.f) * w1[h];
        d += fmaxf(a2 + b2[h], 0.f) * w2[h];
        d += fmaxf(a3 + b3[h], 0.f) * w3[h];
        dd[rr] = d;
    }

    sbuf[r][h]     = dd[0];
    sbuf[r + 4][h] = dd[1];
    __syncthreads();
    float acc0 = fb1[h], acc1 = fb1[h];
    #pragma unroll
    for (int k = 0; k < 64; k++) {
        acc0 = fmaf(sbuf[r][k],     sW1[k * 64 + h], acc0);
        acc1 = fmaf(sbuf[r + 4][k], sW1[k * 64 + h], acc1);
    }
    const float hv0 = fmaxf(acc0, 0.f);
    const float hv1 = fmaxf(acc1, 0.f);
    __syncthreads();
    sbuf[r][h]     = hv0;
    sbuf[r + 4][h] = hv1;
    __syncthreads();
    acc0 = fb2[h]; acc1 = fb2[h];
    #pragma unroll
    for (int k = 0; k < 64; k++) {
        acc0 = fmaf(sbuf[r][k],     sW2[k * 64 + h], acc0);
        acc1 = fmaf(sbuf[r + 4][k], sW2[k * 64 + h], acc1);
    }
    const float h20 = fmaxf(acc0, 0.f);
    const float h21 = fmaxf(acc1, 0.f);

    float v0 = h20 * fW3[h];
    float v1 = h21 * fW3[h];
    #pragma unroll
    for (int off = 16; off; off >>= 1) {
        v0 += __shfl_down_sync(0xffffffffu, v0, off);
        v1 += __shfl_down_sync(0xffffffffu, v1, off);
    }
    if ((t & 31) == 0) { sred[wid] = v0; sred[8 + wid] = v1; }
    __syncthreads();
    if (h == 0) {
        out[b0r + r]     = sred[2 * r] + sred[2 * r + 1] + fb3[0];
        out[b0r + r + 4] = sred[8 + 2 * r] + sred[8 + 2 * r + 1] + fb3[0];
    }

    // Counter reset by the last finish block (all gates passed by then).
    __syncthreads();
    if (t == 0) {
        const int o = atomicAdd(&g_fin, 1);
        if (o == FINBLK - 1) {
            #pragma unroll
            for (int c = 0; c < NGC; c++) atomicExch(&g_cdone[c], 0);
            atomicExch(&g_pdone, 0);
            atomicExch(&g_fin, 0);
        }
    }
}

// =============================================================================
// Launcher (graph-capturable: ONE kernel launch, no sync, no alloc)
// =============================================================================
extern "C" void kernel_launch(void* const* d_in, const int* in_sizes, int n_in,
                              void* d_out, int out_size)
{
    const float* x   = (const float*)d_in[0];
    const float* z1  = (const float*)d_in[1];
    const float* z2  = (const float*)d_in[2];
    const float* z3  = (const float*)d_in[3];
    const float* Wg  = (const float*)d_in[4];
    const float* bg  = (const float*)d_in[5];
    const float* W0  = (const float*)d_in[6];
    const float* b0  = (const float*)d_in[7];
    const float* W1  = (const float*)d_in[8];
    const float* b1  = (const float*)d_in[9];
    const float* W2  = (const float*)d_in[10];
    const float* b2  = (const float*)d_in[11];
    const float* W3  = (const float*)d_in[12];
    const float* b3  = (const float*)d_in[13];
    const float* w1  = (const float*)d_in[14];
    const float* w2  = (const float*)d_in[15];
    const float* w3  = (const float*)d_in[16];
    const float* fW1 = (const float*)d_in[17];
    const float* fb1 = (const float*)d_in[18];
    const float* fW2 = (const float*)d_in[19];
    const float* fb2 = (const float*)d_in[20];
    const float* fW3 = (const float*)d_in[21];
    const float* fb3 = (const float*)d_in[22];
    float* out = (float*)d_out;

    mega_kernel<<<NZBLK + GENEBLK + GGBLK + FINBLK, 256>>>(
        x, z1, z2, z3, Wg, bg, W0, b0, W1, b1, W2, b2, W3, b3,
        w1, w2, w3, fW1, fb1, fW2, fb2, fW3, fb3, out);
}